// round 17
// baseline (speedup 1.0000x reference)
#include <cuda_runtime.h>
#include <cuda_bf16.h>
#include <cstdint>

#define NROW 4096
#define DDIM 2048
#define EPSF 1e-5f

#define BM 128
#define BN 128
#define BKH 64                  // halves per k-chunk (128 bytes/row)
#define NCHUNK (DDIM / BKH)     // 32
#define NSTAGE 3
#define TILEB (BM * 128)        // 16 KB per operand tile
#define STAGEB (2 * TILEB)      // 32 KB per stage
#define NTILE (NROW / BM)       // 32
#define NCTA (NTILE * (NTILE + 1) / 2)   // 528

__device__ __nv_bfloat16 g_xb[NROW * DDIM];   // 16 MB normalized bf16
__device__ float g_acc[NROW * 8];
__device__ int g_done;                         // completion ticket (reset by last CTA)
// [0]=sum pos_intra [1]=cnt pos_intra [2]=sum pos_cross [3]=cnt pos_cross
// [4]=num neg_intra [5]=den neg_intra [6]=num neg_cross [7]=den neg_cross

#define LDSM_X4(R0, R1, R2, R3, addr)                                          \
    asm volatile("ldmatrix.sync.aligned.m8n8.x4.shared.b16 {%0,%1,%2,%3}, [%4];" \
                 : "=r"(R0), "=r"(R1), "=r"(R2), "=r"(R3) : "r"(addr))

#define MMA16816(D, A, B)                                                      \
    asm volatile("mma.sync.aligned.m16n8k16.row.col.f32.bf16.bf16.f32 "        \
                 "{%0,%1,%2,%3},{%4,%5,%6,%7},{%8,%9},{%0,%1,%2,%3};"          \
                 : "+f"((D)[0]), "+f"((D)[1]), "+f"((D)[2]), "+f"((D)[3])      \
                 : "r"((A)[0]), "r"((A)[1]), "r"((A)[2]), "r"((A)[3]),         \
                   "r"((B)[0]), "r"((B)[1]))

__device__ __forceinline__ void cp_async16(uint32_t dst, const void* src) {
    asm volatile("cp.async.cg.shared.global [%0], [%1], 16;"
                 :: "r"(dst), "l"(src) : "memory");
}

// ---------------------------------------------------------------------------
// Kernel 1: L2-normalize rows -> bf16 g_xb; zero g_acc.
// 2 rows per 256-thread block; 128 threads/row; 4 float4 in flight (MLP=4).
// ---------------------------------------------------------------------------
__global__ __launch_bounds__(256) void normalize_kernel(const float* __restrict__ x) {
    int t = threadIdx.x;
    int grp = t >> 7;            // 0 or 1: which row of this block
    int lt = t & 127;
    int row = blockIdx.x * 2 + grp;

    const float4* xr = (const float4*)(x + (size_t)row * DDIM);
    float4 v0 = xr[lt];
    float4 v1 = xr[lt + 128];
    float4 v2 = xr[lt + 256];
    float4 v3 = xr[lt + 384];

    float ss = v0.x * v0.x + v0.y * v0.y + v0.z * v0.z + v0.w * v0.w
             + v1.x * v1.x + v1.y * v1.y + v1.z * v1.z + v1.w * v1.w
             + v2.x * v2.x + v2.y * v2.y + v2.z * v2.z + v2.w * v2.w
             + v3.x * v3.x + v3.y * v3.y + v3.z * v3.z + v3.w * v3.w;
#pragma unroll
    for (int o = 16; o > 0; o >>= 1) ss += __shfl_xor_sync(0xffffffffu, ss, o);

    __shared__ float warpSum[2][4];
    __shared__ float totS[2];
    if ((lt & 31) == 0) warpSum[grp][lt >> 5] = ss;
    __syncthreads();
    if (lt == 0)
        totS[grp] = warpSum[grp][0] + warpSum[grp][1] + warpSum[grp][2] + warpSum[grp][3];
    __syncthreads();

    float rinv = 1.0f / fmaxf(sqrtf(totS[grp]), 1e-12f);
    __nv_bfloat16* orow = g_xb + (size_t)row * DDIM;
    union { uint2 u; __nv_bfloat162 h[2]; } p;
#define STORE4(V, OFF)                                                          \
    p.h[0] = __floats2bfloat162_rn((V).x * rinv, (V).y * rinv);                 \
    p.h[1] = __floats2bfloat162_rn((V).z * rinv, (V).w * rinv);                 \
    *(uint2*)(orow + (OFF)) = p.u;
    STORE4(v0, lt * 4)
    STORE4(v1, (lt + 128) * 4)
    STORE4(v2, (lt + 256) * 4)
    STORE4(v3, (lt + 384) * 4)
#undef STORE4

    if (t < 16) g_acc[blockIdx.x * 16 + t] = 0.f;   // 2 rows x 8 slots
}

// ---------------------------------------------------------------------------
// Kernel 2: triangular Gram (mma.sync bf16, 3-stage cp.async, single barrier
// per chunk, XOR-updated ldmatrix addresses) + loss epilogue + last-CTA
// finalize. 256 threads = 8 warps (4 m x 2 n), warp tile 32x64.
// ---------------------------------------------------------------------------
extern __shared__ char dynsmem[];

__global__ __launch_bounds__(256, 2) void fused_kernel(const int* __restrict__ targets,
                                                       const int* __restrict__ sub,
                                                       float* __restrict__ out) {
    __shared__ float rowAcc[BM][8];
    __shared__ float colAcc[BN][8];
    __shared__ int tI[BM], sI[BM], tJ[BN], sJ[BN];
    __shared__ int isLast;

    // Triangular decode: blockIdx.x -> (bi, bj), bi <= bj
    int bi = 0, rem = blockIdx.x;
    while (rem >= NTILE - bi) { rem -= NTILE - bi; bi++; }
    int bj = bi + rem;
    bool diag = (bi == bj);

    int tid = threadIdx.x;
    int lane = tid & 31;
    int wid = tid >> 5;
    int warp_m = wid & 3;   // m offset 32*warp_m
    int warp_n = wid >> 2;  // n offset 64*warp_n

    uint32_t dynb = (uint32_t)__cvta_generic_to_shared(dynsmem);
    uint32_t base = (dynb + 1023u) & ~1023u;

    for (int i = tid; i < BM * 8; i += 256) {
        ((float*)rowAcc)[i] = 0.f;
        ((float*)colAcc)[i] = 0.f;
    }
    if (tid < BM) {
        tI[tid] = targets[bi * BM + tid];
        sI[tid] = sub[bi * BM + tid];
        tJ[tid] = targets[bj * BN + tid];
        sJ[tid] = sub[bj * BN + tid];
    }

    const __nv_bfloat16* Ag = g_xb + (size_t)(bi * BM) * DDIM;
    const __nv_bfloat16* Bg = g_xb + (size_t)(bj * BN) * DDIM;

    // Per-thread load slots: 4 x 16B per operand per stage.
    int lrow[4], lcoff[4], lcsw[4];
#pragma unroll
    for (int i = 0; i < 4; i++) {
        int idx = i * 256 + tid;
        lrow[i] = idx >> 3;
        int c = idx & 7;
        lcoff[i] = c * 8;
        lcsw[i] = (c ^ (lrow[i] & 7)) * 16;
    }

#define LOAD_STAGE(S, F)                                                           \
    do {                                                                           \
        uint32_t aB = base + (S) * STAGEB;                                         \
        uint32_t bB = aB + TILEB;                                                  \
        int k0 = (F) * BKH;                                                        \
        _Pragma("unroll")                                                          \
        for (int i = 0; i < 4; i++) {                                              \
            int r = lrow[i];                                                       \
            cp_async16(aB + r * 128 + lcsw[i], Ag + (size_t)r * DDIM + k0 + lcoff[i]); \
            cp_async16(bB + r * 128 + lcsw[i], Bg + (size_t)r * DDIM + k0 + lcoff[i]); \
        }                                                                          \
        asm volatile("cp.async.commit_group;" ::: "memory");                       \
    } while (0)

    float acc[2][8][4];
#pragma unroll
    for (int mt = 0; mt < 2; mt++)
#pragma unroll
        for (int nt = 0; nt < 8; nt++)
#pragma unroll
            for (int e = 0; e < 4; e++) acc[mt][nt][e] = 0.f;

    LOAD_STAGE(0, 0);
    LOAD_STAGE(1, 1);

    // Precomputed ldmatrix offsets (ks=0) for the 6 sites.
    int aCeL = lane >> 4;
    int bCeL = (lane >> 3) & 1;
    int aR0 = warp_m * 32 + (lane & 15);
    int aR1 = aR0 + 16;
    int bR0 = warp_n * 64 + ((lane & 7) | ((lane >> 4) << 3));
    uint32_t aOff0 = (uint32_t)(aR0 * 128 + ((aCeL ^ (aR0 & 7)) * 16));
    uint32_t aOff1 = (uint32_t)(aR1 * 128 + ((aCeL ^ (aR1 & 7)) * 16));
    uint32_t bOff0 = (uint32_t)((bR0 + 0)  * 128 + ((bCeL ^ ((bR0 + 0)  & 7)) * 16));
    uint32_t bOff1 = (uint32_t)((bR0 + 16) * 128 + ((bCeL ^ ((bR0 + 16) & 7)) * 16));
    uint32_t bOff2 = (uint32_t)((bR0 + 32) * 128 + ((bCeL ^ ((bR0 + 32) & 7)) * 16));
    uint32_t bOff3 = (uint32_t)((bR0 + 48) * 128 + ((bCeL ^ ((bR0 + 48) & 7)) * 16));

#define XOR_ADDRS(D)                                                               \
    do { aA0 ^= (D); aA1 ^= (D); bA0 ^= (D); bA1 ^= (D); bA2 ^= (D); bA3 ^= (D); } while (0)

#define KSTEP()                                                                    \
    do {                                                                           \
        uint32_t a[2][4], b[8][2];                                                 \
        LDSM_X4(a[0][0], a[0][1], a[0][2], a[0][3], aA0);                          \
        LDSM_X4(a[1][0], a[1][1], a[1][2], a[1][3], aA1);                          \
        LDSM_X4(b[0][0], b[0][1], b[1][0], b[1][1], bA0);                          \
        LDSM_X4(b[2][0], b[2][1], b[3][0], b[3][1], bA1);                          \
        LDSM_X4(b[4][0], b[4][1], b[5][0], b[5][1], bA2);                          \
        LDSM_X4(b[6][0], b[6][1], b[7][0], b[7][1], bA3);                          \
        _Pragma("unroll")                                                          \
        for (int mt = 0; mt < 2; mt++)                                             \
            _Pragma("unroll")                                                      \
            for (int nt = 0; nt < 8; nt++)                                         \
                MMA16816(acc[mt][nt], a[mt], b[nt]);                               \
    } while (0)

    for (int c = 0; c < NCHUNK; c++) {
        if (c + 1 < NCHUNK)
            asm volatile("cp.async.wait_group 1;" ::: "memory");
        else
            asm volatile("cp.async.wait_group 0;" ::: "memory");
        __syncthreads();
        if (c + 2 < NCHUNK) LOAD_STAGE((c + 2) % NSTAGE, c + 2);

        uint32_t asA = base + (c % NSTAGE) * STAGEB;
        uint32_t asB = asA + TILEB;
        uint32_t aA0 = asA + aOff0, aA1 = asA + aOff1;
        uint32_t bA0 = asB + bOff0, bA1 = asB + bOff1;
        uint32_t bA2 = asB + bOff2, bA3 = asB + bOff3;

        KSTEP();            // ks=0
        XOR_ADDRS(0x20u);
        KSTEP();            // ks=1
        XOR_ADDRS(0x60u);
        KSTEP();            // ks=2
        XOR_ADDRS(0x20u);
        KSTEP();            // ks=3
    }

    // Convert dots -> distances in place.
#pragma unroll
    for (int mt = 0; mt < 2; mt++)
#pragma unroll
        for (int nt = 0; nt < 8; nt++)
#pragma unroll
            for (int e = 0; e < 4; e++)
                acc[mt][nt][e] = sqrtf(fmaxf(2.f - 2.f * acc[mt][nt][e], 1e-12f));

    // ---- Row pass ----
#pragma unroll
    for (int mt = 0; mt < 2; mt++) {
#pragma unroll
        for (int h = 0; h < 2; h++) {
            int li = warp_m * 32 + mt * 16 + h * 8 + (lane >> 2);
            int gi = bi * BM + li;
            int ti = tI[li], si = sI[li];
            float p0 = 0.f, p1 = 0.f, p2 = 0.f, p3 = 0.f;
            float p4 = 0.f, p5 = 0.f, p6 = 0.f, p7 = 0.f;
#pragma unroll
            for (int nt = 0; nt < 8; nt++) {
#pragma unroll
                for (int cc = 0; cc < 2; cc++) {
                    int lj = warp_n * 64 + nt * 8 + (lane & 3) * 2 + cc;
                    int gj = bj * BN + lj;
                    float d = acc[mt][nt][h * 2 + cc];
                    bool same = (ti == tJ[lj]);
                    bool intra = (si == sJ[lj]);
                    if (same) {
                        if (gi != gj) {
                            if (intra) { p0 += fmaxf(d - 1.4f, 0.f); p1 += 1.f; }
                            else       { p2 += fmaxf(d - 0.7f, 0.f); p3 += 1.f; }
                        }
                    } else {
                        float alpha = intra ? 2.4f : 2.2f;
                        if (d < alpha) {
                            float diff = alpha - d;
                            float w = __expf(diff);
                            if (intra) { p4 += diff * w; p5 += w; }
                            else       { p6 += diff * w; p7 += w; }
                        }
                    }
                }
            }
#pragma unroll
            for (int o = 1; o <= 2; o <<= 1) {
                p0 += __shfl_xor_sync(0xffffffffu, p0, o);
                p1 += __shfl_xor_sync(0xffffffffu, p1, o);
                p2 += __shfl_xor_sync(0xffffffffu, p2, o);
                p3 += __shfl_xor_sync(0xffffffffu, p3, o);
                p4 += __shfl_xor_sync(0xffffffffu, p4, o);
                p5 += __shfl_xor_sync(0xffffffffu, p5, o);
                p6 += __shfl_xor_sync(0xffffffffu, p6, o);
                p7 += __shfl_xor_sync(0xffffffffu, p7, o);
            }
            if ((lane & 3) == 0) {
                if (p1 != 0.f) { atomicAdd(&rowAcc[li][0], p0); atomicAdd(&rowAcc[li][1], p1); }
                if (p3 != 0.f) { atomicAdd(&rowAcc[li][2], p2); atomicAdd(&rowAcc[li][3], p3); }
                if (p5 != 0.f) { atomicAdd(&rowAcc[li][4], p4); atomicAdd(&rowAcc[li][5], p5); }
                if (p7 != 0.f) { atomicAdd(&rowAcc[li][6], p6); atomicAdd(&rowAcc[li][7], p7); }
            }
        }
    }

    // ---- Column pass (symmetry credit), off-diagonal only ----
    if (!diag) {
#pragma unroll
        for (int nt = 0; nt < 8; nt++) {
#pragma unroll
            for (int cc = 0; cc < 2; cc++) {
                int lj = warp_n * 64 + nt * 8 + (lane & 3) * 2 + cc;
                int tj = tJ[lj], sj = sJ[lj];
                float p0 = 0.f, p1 = 0.f, p2 = 0.f, p3 = 0.f;
                float p4 = 0.f, p5 = 0.f, p6 = 0.f, p7 = 0.f;
#pragma unroll
                for (int mt = 0; mt < 2; mt++) {
#pragma unroll
                    for (int h = 0; h < 2; h++) {
                        int li = warp_m * 32 + mt * 16 + h * 8 + (lane >> 2);
                        float d = acc[mt][nt][h * 2 + cc];
                        bool same = (tI[li] == tj);
                        bool intra = (sI[li] == sj);
                        if (same) {
                            if (intra) { p0 += fmaxf(d - 1.4f, 0.f); p1 += 1.f; }
                            else       { p2 += fmaxf(d - 0.7f, 0.f); p3 += 1.f; }
                        } else {
                            float alpha = intra ? 2.4f : 2.2f;
                            if (d < alpha) {
                                float diff = alpha - d;
                                float w = __expf(diff);
                                if (intra) { p4 += diff * w; p5 += w; }
                                else       { p6 += diff * w; p7 += w; }
                            }
                        }
                    }
                }
#pragma unroll
                for (int o = 4; o <= 16; o <<= 1) {
                    p0 += __shfl_xor_sync(0xffffffffu, p0, o);
                    p1 += __shfl_xor_sync(0xffffffffu, p1, o);
                    p2 += __shfl_xor_sync(0xffffffffu, p2, o);
                    p3 += __shfl_xor_sync(0xffffffffu, p3, o);
                    p4 += __shfl_xor_sync(0xffffffffu, p4, o);
                    p5 += __shfl_xor_sync(0xffffffffu, p5, o);
                    p6 += __shfl_xor_sync(0xffffffffu, p6, o);
                    p7 += __shfl_xor_sync(0xffffffffu, p7, o);
                }
                if (lane < 4) {
                    if (p1 != 0.f) { atomicAdd(&colAcc[lj][0], p0); atomicAdd(&colAcc[lj][1], p1); }
                    if (p3 != 0.f) { atomicAdd(&colAcc[lj][2], p2); atomicAdd(&colAcc[lj][3], p3); }
                    if (p5 != 0.f) { atomicAdd(&colAcc[lj][4], p4); atomicAdd(&colAcc[lj][5], p5); }
                    if (p7 != 0.f) { atomicAdd(&colAcc[lj][6], p6); atomicAdd(&colAcc[lj][7], p7); }
                }
            }
        }
    }

    __syncthreads();

    for (int i = tid; i < BM * 8; i += 256) {
        int r = i >> 3, s = i & 7;
        float v = ((float*)rowAcc)[i];
        if (v != 0.f) atomicAdd(&g_acc[(bi * BM + r) * 8 + s], v);
        if (!diag) {
            float vc = ((float*)colAcc)[i];
            if (vc != 0.f) atomicAdd(&g_acc[(bj * BN + r) * 8 + s], vc);
        }
    }

    // ---- Last-CTA finalize ----
    __threadfence();
    __syncthreads();
    if (tid == 0)
        isLast = (atomicAdd(&g_done, 1) == NCTA - 1) ? 1 : 0;
    __syncthreads();
    if (isLast) {
        float s = 0.f;
        for (int r = tid; r < NROW; r += 256) {
            const float* a = g_acc + r * 8;
            s += a[0] / (a[1] + EPSF) + a[2] / (a[3] + EPSF)
               + a[4] / (a[5] + EPSF) + a[6] / (a[7] + EPSF);
        }
#pragma unroll
        for (int o = 16; o > 0; o >>= 1) s += __shfl_xor_sync(0xffffffffu, s, o);
        // Reuse rowAcc[0][0..7] as warp-sum scratch.
        if ((tid & 31) == 0) rowAcc[0][tid >> 5] = s;
        __syncthreads();
        if (tid == 0) {
            float tot = 0.f;
#pragma unroll
            for (int i = 0; i < 8; i++) tot += rowAcc[0][i];
            out[0] = tot / (float)NROW;
            g_done = 0;   // reset ticket for next graph replay
        }
    }
}

extern "C" void kernel_launch(void* const* d_in, const int* in_sizes, int n_in,
                              void* d_out, int out_size) {
    const float* x       = (const float*)d_in[0];
    const int*   targets = (const int*)d_in[1];
    const int*   sub     = (const int*)d_in[2];

    int dyn = 1024 + NSTAGE * STAGEB;  // 97.3 KB
    cudaFuncSetAttribute(fused_kernel, cudaFuncAttributeMaxDynamicSharedMemorySize, dyn);

    normalize_kernel<<<NROW / 2, 256>>>(x);
    fused_kernel<<<NCTA, 256, dyn>>>(targets, sub, (float*)d_out);
}